// round 7
// baseline (speedup 1.0000x reference)
#include <cuda_runtime.h>
#include <cuda_bf16.h>
#include <cstdint>
#include <math.h>

// ---------------- problem constants ----------------
#define K_TOTAL 150528      // 3*224*224
#define BATCH   64
#define EMB     512
#define HIN_DIM 812         // 512 + 300
#define NCHAN   192         // 64*3
#define NPIX    50176       // 224*224
#define BINS    100

// big GEMM tiling
#define KSPLIT  147
#define KB      1024        // K per CTA (147*1024 = 150528)
#define KC      32          // K per smem chunk
#define NCHUNK  (KB/KC)     // 32
#define NB      256         // N per CTA (2 CTAs cover 512)
#define A_CH    (64*36)     // floats per A chunk buffer (padded)
#define B_CH    (256*36)    // floats per B chunk buffer (padded)
#define SMEM_BYTES ((2*A_CH + 2*B_CH)*4)   // 92160

// ---------------- static device scratch (no runtime alloc) ----------------
__device__ float g_partial[(size_t)KSPLIT * EMB * BATCH];   // [ks][n][b] 19.3MB
__device__ float g_hinT[HIN_DIM * BATCH];                   // [812][64]: rows 0..511 xm, 512..811 hist
__device__ float g_hT[400 * BATCH];                         // h transposed [400][64]
__device__ float g_h1[BATCH * 1400];                        // [64][st600|age400|gen400]

// ---------------- helpers ----------------
__device__ __forceinline__ void cp16(void* dst, const void* src) {
    unsigned d = (unsigned)__cvta_generic_to_shared(dst);
    asm volatile("cp.async.cg.shared.global [%0], [%1], 16;\n" :: "r"(d), "l"(src));
}
__device__ __forceinline__ void cp_commit() { asm volatile("cp.async.commit_group;\n"); }
__device__ __forceinline__ void cp_wait1()  { asm volatile("cp.async.wait_group 1;\n"); }
__device__ __forceinline__ void cp_wait0()  { asm volatile("cp.async.wait_group 0;\n"); }

__device__ __forceinline__ void mma_tf32(float* c, const unsigned* a, unsigned b0, unsigned b1) {
    asm volatile(
        "mma.sync.aligned.m16n8k8.row.col.f32.tf32.tf32.f32 "
        "{%0,%1,%2,%3}, {%4,%5,%6,%7}, {%8,%9}, {%0,%1,%2,%3};\n"
        : "+f"(c[0]), "+f"(c[1]), "+f"(c[2]), "+f"(c[3])
        : "r"(a[0]), "r"(a[1]), "r"(a[2]), "r"(a[3]), "r"(b0), "r"(b1));
}

// ---------------- kernel 1: fused per-channel min/max + 100-bin histogram ----------------
// One CTA per channel. Pass 1: min/max block-reduce. Pass 2: bin (second read
// hits L1/L2 — same CTA, data just streamed). Saves a launch + g_minmax trip
// vs the split version, and makes the second pass cache-resident by design.
__global__ void hist_fused_kernel(const float* __restrict__ x) {
    int ch = blockIdx.x;                 // 0..191 = sample*3 + channel
    int tid = threadIdx.x, wid = tid >> 5;
    const float4* p = (const float4*)(x + (size_t)ch * NPIX);

    __shared__ unsigned sh[8][BINS];
    __shared__ float smn[8], smx[8];
    __shared__ float s_mn, s_scale;

    // zero per-warp histograms
    for (int i = tid; i < 8 * BINS; i += 256) ((unsigned*)sh)[i] = 0u;

    // ---- pass 1: min/max ----
    float mn = 3.4e38f, mx = -3.4e38f;
    for (int i = tid; i < NPIX / 4; i += 256) {
        float4 v = p[i];
        mn = fminf(mn, fminf(fminf(v.x, v.y), fminf(v.z, v.w)));
        mx = fmaxf(mx, fmaxf(fmaxf(v.x, v.y), fmaxf(v.z, v.w)));
    }
    #pragma unroll
    for (int o = 16; o; o >>= 1) {
        mn = fminf(mn, __shfl_xor_sync(0xFFFFFFFFu, mn, o));
        mx = fmaxf(mx, __shfl_xor_sync(0xFFFFFFFFu, mx, o));
    }
    if ((tid & 31) == 0) { smn[wid] = mn; smx[wid] = mx; }
    __syncthreads();
    if (tid == 0) {
        #pragma unroll
        for (int r = 1; r < 8; r++) { mn = fminf(mn, smn[r]); mx = fmaxf(mx, smx[r]); }
        float width = (mx > mn) ? (mx - mn) : 1.0f;
        s_mn = mn;
        s_scale = (float)BINS / width;
    }
    __syncthreads();

    float bmn = s_mn, scale = s_scale;

    // ---- pass 2: bin (cache-resident re-read) ----
    for (int i = tid; i < NPIX / 4; i += 256) {
        float4 v = p[i];
        int b0 = min((int)((v.x - bmn) * scale), BINS - 1);
        int b1 = min((int)((v.y - bmn) * scale), BINS - 1);
        int b2 = min((int)((v.z - bmn) * scale), BINS - 1);
        int b3 = min((int)((v.w - bmn) * scale), BINS - 1);
        atomicAdd(&sh[wid][b0], 1u);
        atomicAdd(&sh[wid][b1], 1u);
        atomicAdd(&sh[wid][b2], 1u);
        atomicAdd(&sh[wid][b3], 1u);
    }
    __syncthreads();

    int c3 = ch % 3, bs = ch / 3;
    for (int bin = tid; bin < BINS; bin += 256) {
        unsigned s = 0;
        #pragma unroll
        for (int w = 0; w < 8; w++) s += sh[w][bin];
        g_hinT[(size_t)(EMB + c3 * BINS + bin) * BATCH + bs] = (float)s;
    }
}

// ---------------- kernel 2: big GEMM (xm = x @ base_W^T), split-K partials ----------------
// grid (2, 147), 256 threads, dynamic smem SMEM_BYTES
__global__ void __launch_bounds__(256, 2)
gemm_big(const float* __restrict__ x, const float* __restrict__ W) {
    extern __shared__ float smem[];
    float* As = smem;                 // [2][64][36]
    float* Bs = smem + 2 * A_CH;      // [2][256][36]

    int tid  = threadIdx.x;
    int wid  = tid >> 5, lane = tid & 31;
    int wm   = wid >> 2;              // 0..1 : rows wm*32..+32
    int wn   = wid & 3;               // 0..3 : cols wn*64..+64
    int g    = lane >> 2, t = lane & 3;

    int nbase = blockIdx.x * NB;
    int kbase = blockIdx.y * KB;

    float acc[2][8][4];
    #pragma unroll
    for (int i = 0; i < 2; i++)
        #pragma unroll
        for (int j = 0; j < 8; j++)
            #pragma unroll
            for (int q = 0; q < 4; q++) acc[i][j][q] = 0.0f;

    // chunk loader
    auto load_chunk = [&](int buf, int kg) {
        #pragma unroll
        for (int i = 0; i < 2; i++) {               // A: 512 float4
            int f = tid + i * 256;
            int row = f >> 3, seg = f & 7;
            cp16(As + buf * A_CH + row * 36 + seg * 4,
                 x + (size_t)row * K_TOTAL + kg + seg * 4);
        }
        #pragma unroll
        for (int i = 0; i < 8; i++) {               // B: 2048 float4
            int f = tid + i * 256;
            int row = f >> 3, seg = f & 7;
            cp16(Bs + buf * B_CH + row * 36 + seg * 4,
                 W + (size_t)(nbase + row) * K_TOTAL + kg + seg * 4);
        }
        cp_commit();
    };

    load_chunk(0, kbase);

    for (int c = 0; c < NCHUNK; c++) {
        int buf = c & 1;
        if (c + 1 < NCHUNK) { load_chunk(buf ^ 1, kbase + (c + 1) * KC); cp_wait1(); }
        else cp_wait0();
        __syncthreads();

        const float* ab = As + buf * A_CH + (wm * 32) * 36;
        const float* bb = Bs + buf * B_CH + (wn * 64) * 36;

        #pragma unroll
        for (int ks = 0; ks < 4; ks++) {
            int kc = ks * 8;
            unsigned a[2][4];
            #pragma unroll
            for (int mf = 0; mf < 2; mf++) {
                const float* ap = ab + (mf * 16 + g) * 36 + kc + t;
                a[mf][0] = __float_as_uint(ap[0]);
                a[mf][1] = __float_as_uint(ap[8 * 36]);
                a[mf][2] = __float_as_uint(ap[4]);
                a[mf][3] = __float_as_uint(ap[8 * 36 + 4]);
            }
            #pragma unroll
            for (int nf = 0; nf < 8; nf++) {
                const float* bp = bb + (nf * 8 + g) * 36 + kc + t;
                unsigned b0 = __float_as_uint(bp[0]);
                unsigned b1 = __float_as_uint(bp[4]);
                mma_tf32(acc[0][nf], a[0], b0, b1);
                mma_tf32(acc[1][nf], a[1], b0, b1);
            }
        }
        __syncthreads();
    }

    // epilogue: partials [ks][n][b]
    size_t ks = blockIdx.y;
    #pragma unroll
    for (int mf = 0; mf < 2; mf++)
        #pragma unroll
        for (int nf = 0; nf < 8; nf++)
            #pragma unroll
            for (int ci = 0; ci < 4; ci++) {
                int b = wm * 32 + mf * 16 + g + ((ci >= 2) ? 8 : 0);
                int n = nbase + wn * 64 + nf * 8 + 2 * t + (ci & 1);
                g_partial[(ks * EMB + n) * BATCH + b] = acc[mf][nf][ci];
            }
}

// ---------------- kernel 3: split-K reduce -> hinT rows 0..511 ----------------
__global__ void reduce_kernel(const float* __restrict__ base_b) {
    int tidg = blockIdx.x * 256 + threadIdx.x;       // 0..32767
    if (tidg >= EMB * BATCH) return;
    int n = tidg >> 6, b = tidg & 63;
    float s = base_b[n];
    const float* p = g_partial + (size_t)n * BATCH + b;
    #pragma unroll 7
    for (int ks = 0; ks < KSPLIT; ks++) s += p[(size_t)ks * EMB * BATCH];
    g_hinT[(size_t)n * BATCH + b] = s;
}

// ---------------- kernel 4: small GEMM (relu(A^T-layout @ W^T + bias)) ----------------
// A_T: [K][64], W: [N][K], out row-major [64][ldo] at column offset coff, out_T: [N][64]
__global__ void gemm_small(const float* __restrict__ A_T, const float* __restrict__ W,
                           const float* __restrict__ bias,
                           float* __restrict__ out, int ldo, int coff,
                           float* __restrict__ out_T, int K, int N) {
    int wg   = (blockIdx.x * blockDim.x + threadIdx.x) >> 5;
    int lane = threadIdx.x & 31;
    int n0   = (wg >> 1) * 4;
    int b    = (wg & 1) * 32 + lane;
    if (n0 >= N) return;

    float acc[4];
    #pragma unroll
    for (int j = 0; j < 4; j++) acc[j] = bias[n0 + j];

    const float4* w0 = (const float4*)(W + (size_t)(n0 + 0) * K);
    const float4* w1 = (const float4*)(W + (size_t)(n0 + 1) * K);
    const float4* w2 = (const float4*)(W + (size_t)(n0 + 2) * K);
    const float4* w3 = (const float4*)(W + (size_t)(n0 + 3) * K);

    #pragma unroll 4
    for (int k = 0; k < K; k += 4) {
        float a0 = A_T[(size_t)(k + 0) * BATCH + b];
        float a1 = A_T[(size_t)(k + 1) * BATCH + b];
        float a2 = A_T[(size_t)(k + 2) * BATCH + b];
        float a3 = A_T[(size_t)(k + 3) * BATCH + b];
        int q = k >> 2;
        float4 v0 = w0[q], v1 = w1[q], v2 = w2[q], v3 = w3[q];
        acc[0] += a0 * v0.x + a1 * v0.y + a2 * v0.z + a3 * v0.w;
        acc[1] += a0 * v1.x + a1 * v1.y + a2 * v1.z + a3 * v1.w;
        acc[2] += a0 * v2.x + a1 * v2.y + a2 * v2.z + a3 * v2.w;
        acc[3] += a0 * v3.x + a1 * v3.y + a2 * v3.z + a3 * v3.w;
    }
    #pragma unroll
    for (int j = 0; j < 4; j++) {
        float v = fmaxf(acc[j], 0.0f);
        if (out)   out[(size_t)b * ldo + coff + n0 + j] = v;
        if (out_T) out_T[(size_t)(n0 + j) * BATCH + b] = v;
    }
}

// ---------------- kernel 5: final logits + softmax, all three heads ----------------
__global__ void heads_kernel(const float* __restrict__ stW2, const float* __restrict__ stb2,
                             const float* __restrict__ ageW2, const float* __restrict__ ageb2,
                             const float* __restrict__ genW2, const float* __restrict__ genb2,
                             float* __restrict__ out) {
    int b = blockIdx.x, lane = threadIdx.x;
    const float* hrow = g_h1 + (size_t)b * 1400;

    // ---- st: 10 logits, K=600 ----
    {
        float l[10];
        #pragma unroll
        for (int n = 0; n < 10; n++) {
            float p = 0.0f;
            for (int k = lane; k < 600; k += 32) p += hrow[k] * stW2[n * 600 + k];
            #pragma unroll
            for (int o = 16; o; o >>= 1) p += __shfl_xor_sync(0xFFFFFFFFu, p, o);
            l[n] = fmaxf(p + stb2[n], 0.0f);
        }
        float m = l[0];
        #pragma unroll
        for (int n = 1; n < 10; n++) m = fmaxf(m, l[n]);
        float s = 0.0f;
        #pragma unroll
        for (int n = 0; n < 10; n++) { l[n] = __expf(l[n] - m); s += l[n]; }
        float inv = 1.0f / s;
        if (lane == 0) {
            #pragma unroll
            for (int n = 0; n < 10; n++) out[b * 10 + n] = l[n] * inv;
        }
    }
    // ---- age: 4 logits, K=400 ----
    {
        const float* hr = hrow + 600;
        float l[4];
        #pragma unroll
        for (int n = 0; n < 4; n++) {
            float p = 0.0f;
            for (int k = lane; k < 400; k += 32) p += hr[k] * ageW2[n * 400 + k];
            #pragma unroll
            for (int o = 16; o; o >>= 1) p += __shfl_xor_sync(0xFFFFFFFFu, p, o);
            l[n] = fmaxf(p + ageb2[n], 0.0f);
        }
        float m = fmaxf(fmaxf(l[0], l[1]), fmaxf(l[2], l[3]));
        float s = 0.0f;
        #pragma unroll
        for (int n = 0; n < 4; n++) { l[n] = __expf(l[n] - m); s += l[n]; }
        float inv = 1.0f / s;
        if (lane == 0) {
            #pragma unroll
            for (int n = 0; n < 4; n++) out[640 + b * 4 + n] = l[n] * inv;
        }
    }
    // ---- gender: 2 logits, K=400 ----
    {
        const float* hr = hrow + 1000;
        float l[2];
        #pragma unroll
        for (int n = 0; n < 2; n++) {
            float p = 0.0f;
            for (int k = lane; k < 400; k += 32) p += hr[k] * genW2[n * 400 + k];
            #pragma unroll
            for (int o = 16; o; o >>= 1) p += __shfl_xor_sync(0xFFFFFFFFu, p, o);
            l[n] = fmaxf(p + genb2[n], 0.0f);
        }
        float m = fmaxf(l[0], l[1]);
        float e0 = __expf(l[0] - m), e1 = __expf(l[1] - m);
        float inv = 1.0f / (e0 + e1);
        if (lane == 0) {
            out[896 + b * 2 + 0] = e0 * inv;
            out[896 + b * 2 + 1] = e1 * inv;
        }
    }
}

// ---------------- launch ----------------
extern "C" void kernel_launch(void* const* d_in, const int* in_sizes, int n_in,
                              void* d_out, int out_size) {
    const float* x      = (const float*)d_in[0];
    const float* base_W = (const float*)d_in[1];
    const float* base_b = (const float*)d_in[2];
    const float* hW     = (const float*)d_in[3];
    const float* hb     = (const float*)d_in[4];
    const float* stW1   = (const float*)d_in[5];
    const float* stb1   = (const float*)d_in[6];
    const float* stW2   = (const float*)d_in[7];
    const float* stb2   = (const float*)d_in[8];
    const float* ageW1  = (const float*)d_in[9];
    const float* ageb1  = (const float*)d_in[10];
    const float* ageW2  = (const float*)d_in[11];
    const float* ageb2  = (const float*)d_in[12];
    const float* genW1  = (const float*)d_in[13];
    const float* genb1  = (const float*)d_in[14];
    const float* genW2  = (const float*)d_in[15];
    const float* genb2  = (const float*)d_in[16];
    float* out = (float*)d_out;

    // capture-safe (not a stream op, not an allocation); unconditional each call
    cudaFuncSetAttribute(gemm_big, cudaFuncAttributeMaxDynamicSharedMemorySize, SMEM_BYTES);

    // resolve device scratch symbols (host shadows of __device__ globals are NOT
    // valid device pointers — must go through cudaGetSymbolAddress)
    float *hinT, *hT, *h1;
    cudaGetSymbolAddress((void**)&hinT, g_hinT);
    cudaGetSymbolAddress((void**)&hT,   g_hT);
    cudaGetSymbolAddress((void**)&h1,   g_h1);

    hist_fused_kernel<<<NCHAN, 256>>>(x);
    gemm_big<<<dim3(2, KSPLIT), 256, SMEM_BYTES>>>(x, base_W);
    reduce_kernel<<<(EMB * BATCH + 255) / 256, 256>>>(base_b);

    // h = relu(hin @ hW^T + hb): K=812, N=400 -> write transposed g_hT
    {
        int warps = (400 / 4) * 2;                    // 200
        int blocks = (warps * 32 + 255) / 256;        // 25
        gemm_small<<<blocks, 256>>>(hinT, hW, hb, nullptr, 0, 0, hT, HIN_DIM, 400);
    }
    // heads hidden layers: K=400, into g_h1 row-major
    {
        int warps = (600 / 4) * 2;                    // 300
        gemm_small<<<(warps * 32 + 255) / 256, 256>>>(hT, stW1, stb1, h1, 1400, 0,    nullptr, 400, 600);
        warps = (400 / 4) * 2;                        // 200
        gemm_small<<<(warps * 32 + 255) / 256, 256>>>(hT, ageW1, ageb1, h1, 1400, 600,  nullptr, 400, 400);
        gemm_small<<<(warps * 32 + 255) / 256, 256>>>(hT, genW1, genb1, h1, 1400, 1000, nullptr, 400, 400);
    }
    heads_kernel<<<BATCH, 32>>>(stW2, stb2, ageW2, ageb2, genW2, genb2, out);
}

// round 8
// speedup vs baseline: 1.1953x; 1.1953x over previous
#include <cuda_runtime.h>
#include <cuda_bf16.h>
#include <cstdint>
#include <math.h>

// ---------------- problem constants ----------------
#define K_TOTAL 150528      // 3*224*224
#define BATCH   64
#define EMB     512
#define NCHAN   192         // 64*3
#define NPIX    50176       // 224*224
#define BINS    100

// big GEMM tiling
#define KSPLIT  147
#define KB      1024        // K per CTA (147*1024 = 150528)
#define KC      32          // K per smem chunk
#define NCHUNK  (KB/KC)     // 32
#define NB      256         // N per CTA (2 CTAs cover 512)
#define A_CH    (64*36)     // floats per A chunk buffer (padded)
#define B_CH    (256*36)    // floats per B chunk buffer (padded)
#define SMEM_BYTES ((2*A_CH + 2*B_CH)*4)   // 92160

// ---------------- static device scratch (no runtime alloc) ----------------
__device__ float g_partial[(size_t)KSPLIT * BATCH * EMB];   // [ks][b][n] 19.3MB
__device__ float g_hist[BATCH * 300];                       // [64][300]
__device__ float g_h[BATCH * 400];                          // [64][400] h row-major

// ---------------- helpers ----------------
__device__ __forceinline__ void cp16(void* dst, const void* src) {
    unsigned d = (unsigned)__cvta_generic_to_shared(dst);
    asm volatile("cp.async.cg.shared.global [%0], [%1], 16;\n" :: "r"(d), "l"(src));
}
__device__ __forceinline__ void cp_commit() { asm volatile("cp.async.commit_group;\n"); }
__device__ __forceinline__ void cp_wait1()  { asm volatile("cp.async.wait_group 1;\n"); }
__device__ __forceinline__ void cp_wait0()  { asm volatile("cp.async.wait_group 0;\n"); }

__device__ __forceinline__ void mma_tf32(float* c, const unsigned* a, unsigned b0, unsigned b1) {
    asm volatile(
        "mma.sync.aligned.m16n8k8.row.col.f32.tf32.tf32.f32 "
        "{%0,%1,%2,%3}, {%4,%5,%6,%7}, {%8,%9}, {%0,%1,%2,%3};\n"
        : "+f"(c[0]), "+f"(c[1]), "+f"(c[2]), "+f"(c[3])
        : "r"(a[0]), "r"(a[1]), "r"(a[2]), "r"(a[3]), "r"(b0), "r"(b1));
}

// ---------------- kernel 1: fused per-channel min/max + 100-bin histogram ----------------
__global__ void hist_fused_kernel(const float* __restrict__ x) {
    int ch = blockIdx.x;                 // 0..191 = sample*3 + channel
    int tid = threadIdx.x, wid = tid >> 5;
    const float4* p = (const float4*)(x + (size_t)ch * NPIX);

    __shared__ unsigned sh[8][BINS];
    __shared__ float smn[8], smx[8];
    __shared__ float s_mn, s_scale;

    for (int i = tid; i < 8 * BINS; i += 256) ((unsigned*)sh)[i] = 0u;

    // ---- pass 1: min/max ----
    float mn = 3.4e38f, mx = -3.4e38f;
    for (int i = tid; i < NPIX / 4; i += 256) {
        float4 v = p[i];
        mn = fminf(mn, fminf(fminf(v.x, v.y), fminf(v.z, v.w)));
        mx = fmaxf(mx, fmaxf(fmaxf(v.x, v.y), fmaxf(v.z, v.w)));
    }
    #pragma unroll
    for (int o = 16; o; o >>= 1) {
        mn = fminf(mn, __shfl_xor_sync(0xFFFFFFFFu, mn, o));
        mx = fmaxf(mx, __shfl_xor_sync(0xFFFFFFFFu, mx, o));
    }
    if ((tid & 31) == 0) { smn[wid] = mn; smx[wid] = mx; }
    __syncthreads();
    if (tid == 0) {
        #pragma unroll
        for (int r = 1; r < 8; r++) { mn = fminf(mn, smn[r]); mx = fmaxf(mx, smx[r]); }
        float width = (mx > mn) ? (mx - mn) : 1.0f;
        s_mn = mn;
        s_scale = (float)BINS / width;
    }
    __syncthreads();

    float bmn = s_mn, scale = s_scale;

    // ---- pass 2: bin (cache-resident re-read) ----
    for (int i = tid; i < NPIX / 4; i += 256) {
        float4 v = p[i];
        int b0 = min((int)((v.x - bmn) * scale), BINS - 1);
        int b1 = min((int)((v.y - bmn) * scale), BINS - 1);
        int b2 = min((int)((v.z - bmn) * scale), BINS - 1);
        int b3 = min((int)((v.w - bmn) * scale), BINS - 1);
        atomicAdd(&sh[wid][b0], 1u);
        atomicAdd(&sh[wid][b1], 1u);
        atomicAdd(&sh[wid][b2], 1u);
        atomicAdd(&sh[wid][b3], 1u);
    }
    __syncthreads();

    int c3 = ch % 3, bs = ch / 3;
    for (int bin = tid; bin < BINS; bin += 256) {
        unsigned s = 0;
        #pragma unroll
        for (int w = 0; w < 8; w++) s += sh[w][bin];
        g_hist[bs * 300 + c3 * BINS + bin] = (float)s;
    }
}

// ---------------- kernel 2: big GEMM (xm = x @ base_W^T), split-K partials ----------------
// grid (2, 147), 256 threads, dynamic smem SMEM_BYTES
__global__ void __launch_bounds__(256, 2)
gemm_big(const float* __restrict__ x, const float* __restrict__ W) {
    extern __shared__ float smem[];
    float* As = smem;                 // [2][64][36]
    float* Bs = smem + 2 * A_CH;      // [2][256][36]

    int tid  = threadIdx.x;
    int wid  = tid >> 5, lane = tid & 31;
    int wm   = wid >> 2;              // 0..1 : rows wm*32..+32
    int wn   = wid & 3;               // 0..3 : cols wn*64..+64
    int g    = lane >> 2, t = lane & 3;

    int nbase = blockIdx.x * NB;
    int kbase = blockIdx.y * KB;

    float acc[2][8][4];
    #pragma unroll
    for (int i = 0; i < 2; i++)
        #pragma unroll
        for (int j = 0; j < 8; j++)
            #pragma unroll
            for (int q = 0; q < 4; q++) acc[i][j][q] = 0.0f;

    auto load_chunk = [&](int buf, int kg) {
        #pragma unroll
        for (int i = 0; i < 2; i++) {               // A: 512 float4
            int f = tid + i * 256;
            int row = f >> 3, seg = f & 7;
            cp16(As + buf * A_CH + row * 36 + seg * 4,
                 x + (size_t)row * K_TOTAL + kg + seg * 4);
        }
        #pragma unroll
        for (int i = 0; i < 8; i++) {               // B: 2048 float4
            int f = tid + i * 256;
            int row = f >> 3, seg = f & 7;
            cp16(Bs + buf * B_CH + row * 36 + seg * 4,
                 W + (size_t)(nbase + row) * K_TOTAL + kg + seg * 4);
        }
        cp_commit();
    };

    load_chunk(0, kbase);

    for (int c = 0; c < NCHUNK; c++) {
        int buf = c & 1;
        if (c + 1 < NCHUNK) { load_chunk(buf ^ 1, kbase + (c + 1) * KC); cp_wait1(); }
        else cp_wait0();
        __syncthreads();

        const float* ab = As + buf * A_CH + (wm * 32) * 36;
        const float* bb = Bs + buf * B_CH + (wn * 64) * 36;

        #pragma unroll
        for (int ks = 0; ks < 4; ks++) {
            int kc = ks * 8;
            unsigned a[2][4];
            #pragma unroll
            for (int mf = 0; mf < 2; mf++) {
                const float* ap = ab + (mf * 16 + g) * 36 + kc + t;
                a[mf][0] = __float_as_uint(ap[0]);
                a[mf][1] = __float_as_uint(ap[8 * 36]);
                a[mf][2] = __float_as_uint(ap[4]);
                a[mf][3] = __float_as_uint(ap[8 * 36 + 4]);
            }
            #pragma unroll
            for (int nf = 0; nf < 8; nf++) {
                const float* bp = bb + (nf * 8 + g) * 36 + kc + t;
                unsigned b0 = __float_as_uint(bp[0]);
                unsigned b1 = __float_as_uint(bp[4]);
                mma_tf32(acc[0][nf], a[0], b0, b1);
                mma_tf32(acc[1][nf], a[1], b0, b1);
            }
        }
        __syncthreads();
    }

    // epilogue: partials [ks][b][n]
    size_t ks = blockIdx.y;
    #pragma unroll
    for (int mf = 0; mf < 2; mf++)
        #pragma unroll
        for (int nf = 0; nf < 8; nf++)
            #pragma unroll
            for (int ci = 0; ci < 4; ci++) {
                int b = wm * 32 + mf * 16 + g + ((ci >= 2) ? 8 : 0);
                int n = nbase + wn * 64 + nf * 8 + 2 * t + (ci & 1);
                g_partial[(ks * BATCH + b) * EMB + n] = acc[mf][nf][ci];
            }
}

// ---------------- kernel 3: fused split-K reduce + layer1 (h = relu(hin @ hW^T + hb)) ----------------
// grid 64 (one CTA per sample), 256 threads
__global__ void mlp1_kernel(const float* __restrict__ base_b,
                            const float* __restrict__ hW,
                            const float* __restrict__ hb) {
    int b = blockIdx.x, tid = threadIdx.x;
    __shared__ __align__(16) float hin_s[816];   // [0:512) xm, [512:812) hist

    // split-K reduce for this sample: coalesced 512-float rows per ks
    for (int n = tid; n < EMB; n += 256) {
        float s = base_b[n];
        const float* p = g_partial + (size_t)b * EMB + n;
        #pragma unroll 7
        for (int ks = 0; ks < KSPLIT; ks++) s += p[(size_t)ks * BATCH * EMB];
        hin_s[n] = s;
    }
    for (int j = tid; j < 300; j += 256) hin_s[EMB + j] = g_hist[b * 300 + j];
    __syncthreads();

    // layer1: 400 outputs, 2 per thread (independent chains + 2 W streams)
    if (tid < 200) {
        int n0 = 2 * tid, n1 = n0 + 1;
        float acc0 = hb[n0], acc1 = hb[n1];
        const float4* hv = (const float4*)hin_s;
        const float4* w0 = (const float4*)(hW + (size_t)n0 * 812);
        const float4* w1 = (const float4*)(hW + (size_t)n1 * 812);
        #pragma unroll 4
        for (int q = 0; q < 203; q++) {
            float4 h4 = hv[q], a = w0[q], c = w1[q];
            acc0 += h4.x * a.x + h4.y * a.y + h4.z * a.z + h4.w * a.w;
            acc1 += h4.x * c.x + h4.y * c.y + h4.z * c.z + h4.w * c.w;
        }
        g_h[b * 400 + n0] = fmaxf(acc0, 0.0f);
        g_h[b * 400 + n1] = fmaxf(acc1, 0.0f);
    }
}

// ---------------- kernel 4: fused head (hidden + logits + softmax) ----------------
// grid (3 heads, 64 samples), 256 threads
__global__ void heads_fused(const float* __restrict__ stW1, const float* __restrict__ stb1,
                            const float* __restrict__ stW2, const float* __restrict__ stb2,
                            const float* __restrict__ ageW1, const float* __restrict__ ageb1,
                            const float* __restrict__ ageW2, const float* __restrict__ ageb2,
                            const float* __restrict__ genW1, const float* __restrict__ genb1,
                            const float* __restrict__ genW2, const float* __restrict__ genb2,
                            float* __restrict__ out) {
    int head = blockIdx.x, b = blockIdx.y, tid = threadIdx.x;
    __shared__ __align__(16) float h_s[400];
    __shared__ __align__(16) float hid_s[600];
    __shared__ float logit_s[10];

    const float *W1, *b1, *W2, *b2;
    int Nh, NL;
    float* outp;
    if (head == 0)      { W1 = stW1;  b1 = stb1;  W2 = stW2;  b2 = stb2;  Nh = 600; NL = 10; outp = out + b * 10; }
    else if (head == 1) { W1 = ageW1; b1 = ageb1; W2 = ageW2; b2 = ageb2; Nh = 400; NL = 4;  outp = out + 640 + b * 4; }
    else                { W1 = genW1; b1 = genb1; W2 = genW2; b2 = genb2; Nh = 400; NL = 2;  outp = out + 896 + b * 2; }

    for (int i = tid; i < 400; i += 256) h_s[i] = g_h[b * 400 + i];
    __syncthreads();

    // hidden layer: Nh outputs, K=400
    for (int o = tid; o < Nh; o += 256) {
        float acc = b1[o];
        const float4* hv = (const float4*)h_s;
        const float4* w  = (const float4*)(W1 + (size_t)o * 400);
        #pragma unroll 4
        for (int q = 0; q < 100; q++) {
            float4 h4 = hv[q], c = w[q];
            acc += h4.x * c.x + h4.y * c.y + h4.z * c.z + h4.w * c.w;
        }
        hid_s[o] = fmaxf(acc, 0.0f);
    }
    __syncthreads();

    // logits: one warp per logit (strided over 8 warps)
    int wid = tid >> 5, lane = tid & 31;
    for (int n = wid; n < NL; n += 8) {
        float p = 0.0f;
        for (int k = lane; k < Nh; k += 32) p += hid_s[k] * W2[n * Nh + k];
        #pragma unroll
        for (int o = 16; o; o >>= 1) p += __shfl_xor_sync(0xFFFFFFFFu, p, o);
        if (lane == 0) logit_s[n] = fmaxf(p + b2[n], 0.0f);
    }
    __syncthreads();

    if (tid == 0) {
        float m = logit_s[0];
        for (int n = 1; n < NL; n++) m = fmaxf(m, logit_s[n]);
        float e[10], s = 0.0f;
        for (int n = 0; n < NL; n++) { e[n] = __expf(logit_s[n] - m); s += e[n]; }
        float inv = 1.0f / s;
        for (int n = 0; n < NL; n++) outp[n] = e[n] * inv;
    }
}

// ---------------- launch ----------------
extern "C" void kernel_launch(void* const* d_in, const int* in_sizes, int n_in,
                              void* d_out, int out_size) {
    const float* x      = (const float*)d_in[0];
    const float* base_W = (const float*)d_in[1];
    const float* base_b = (const float*)d_in[2];
    const float* hW     = (const float*)d_in[3];
    const float* hb     = (const float*)d_in[4];
    const float* stW1   = (const float*)d_in[5];
    const float* stb1   = (const float*)d_in[6];
    const float* stW2   = (const float*)d_in[7];
    const float* stb2   = (const float*)d_in[8];
    const float* ageW1  = (const float*)d_in[9];
    const float* ageb1  = (const float*)d_in[10];
    const float* ageW2  = (const float*)d_in[11];
    const float* ageb2  = (const float*)d_in[12];
    const float* genW1  = (const float*)d_in[13];
    const float* genb1  = (const float*)d_in[14];
    const float* genW2  = (const float*)d_in[15];
    const float* genb2  = (const float*)d_in[16];
    float* out = (float*)d_out;

    cudaFuncSetAttribute(gemm_big, cudaFuncAttributeMaxDynamicSharedMemorySize, SMEM_BYTES);

    hist_fused_kernel<<<NCHAN, 256>>>(x);
    gemm_big<<<dim3(2, KSPLIT), 256, SMEM_BYTES>>>(x, base_W);
    mlp1_kernel<<<BATCH, 256>>>(base_b, hW, hb);
    heads_fused<<<dim3(3, BATCH), 256>>>(stW1, stb1, stW2, stb2,
                                         ageW1, ageb1, ageW2, ageb2,
                                         genW1, genb1, genW2, genb2, out);
}

// round 11
// speedup vs baseline: 2.3135x; 1.9355x over previous
#include <cuda_runtime.h>
#include <cuda_bf16.h>
#include <cstdint>
#include <math.h>

// ---------------- problem constants ----------------
#define K_TOTAL 150528      // 3*224*224
#define BATCH   64
#define EMB     512
#define NCHAN   192         // 64*3
#define NPIX    50176       // 224*224
#define BINS    100

// big GEMM tiling
#define KSPLIT  147
#define KB      1024        // K per CTA (147*1024 = 150528)
#define KC      32          // K per smem chunk
#define NCHUNK  (KB/KC)     // 32
#define NB      256         // N per CTA (2 CTAs cover 512)
#define A_CH    (64*36)     // floats per A chunk buffer (padded)
#define B_CH    (256*36)    // floats per B chunk buffer (padded)
#define SMEM_BYTES ((2*A_CH + 2*B_CH)*4)   // 92160

// ---------------- static device scratch (no runtime alloc) ----------------
__device__ float g_partial[(size_t)KSPLIT * BATCH * EMB];   // [ks][b][n] 19.3MB
__device__ float g_hist[BATCH * 300];                       // [64][300]
__device__ float g_hin[BATCH * 812];                        // [64][812]
__device__ float g_h[BATCH * 400];                          // [64][400]
__device__ float g_hid[BATCH * 1400];                       // [64][st600|age400|gen400]

// ---------------- helpers ----------------
__device__ __forceinline__ void cp16(void* dst, const void* src) {
    unsigned d = (unsigned)__cvta_generic_to_shared(dst);
    asm volatile("cp.async.cg.shared.global [%0], [%1], 16;\n" :: "r"(d), "l"(src));
}
__device__ __forceinline__ void cp_commit() { asm volatile("cp.async.commit_group;\n"); }
__device__ __forceinline__ void cp_wait1()  { asm volatile("cp.async.wait_group 1;\n"); }
__device__ __forceinline__ void cp_wait0()  { asm volatile("cp.async.wait_group 0;\n"); }

__device__ __forceinline__ void mma_tf32(float* c, const unsigned* a, unsigned b0, unsigned b1) {
    asm volatile(
        "mma.sync.aligned.m16n8k8.row.col.f32.tf32.tf32.f32 "
        "{%0,%1,%2,%3}, {%4,%5,%6,%7}, {%8,%9}, {%0,%1,%2,%3};\n"
        : "+f"(c[0]), "+f"(c[1]), "+f"(c[2]), "+f"(c[3])
        : "r"(a[0]), "r"(a[1]), "r"(a[2]), "r"(a[3]), "r"(b0), "r"(b1));
}

// ---------------- kernel 1: fused per-channel min/max + 100-bin histogram ----------------
__global__ void hist_fused_kernel(const float* __restrict__ x) {
    int ch = blockIdx.x;
    int tid = threadIdx.x, wid = tid >> 5;
    const float4* p = (const float4*)(x + (size_t)ch * NPIX);

    __shared__ unsigned sh[8][BINS];
    __shared__ float smn[8], smx[8];
    __shared__ float s_mn, s_scale;

    for (int i = tid; i < 8 * BINS; i += 256) ((unsigned*)sh)[i] = 0u;

    float mn = 3.4e38f, mx = -3.4e38f;
    for (int i = tid; i < NPIX / 4; i += 256) {
        float4 v = p[i];
        mn = fminf(mn, fminf(fminf(v.x, v.y), fminf(v.z, v.w)));
        mx = fmaxf(mx, fmaxf(fmaxf(v.x, v.y), fmaxf(v.z, v.w)));
    }
    #pragma unroll
    for (int o = 16; o; o >>= 1) {
        mn = fminf(mn, __shfl_xor_sync(0xFFFFFFFFu, mn, o));
        mx = fmaxf(mx, __shfl_xor_sync(0xFFFFFFFFu, mx, o));
    }
    if ((tid & 31) == 0) { smn[wid] = mn; smx[wid] = mx; }
    __syncthreads();
    if (tid == 0) {
        #pragma unroll
        for (int r = 1; r < 8; r++) { mn = fminf(mn, smn[r]); mx = fmaxf(mx, smx[r]); }
        float width = (mx > mn) ? (mx - mn) : 1.0f;
        s_mn = mn;
        s_scale = (float)BINS / width;
    }
    __syncthreads();

    float bmn = s_mn, scale = s_scale;
    for (int i = tid; i < NPIX / 4; i += 256) {
        float4 v = p[i];
        int b0 = min((int)((v.x - bmn) * scale), BINS - 1);
        int b1 = min((int)((v.y - bmn) * scale), BINS - 1);
        int b2 = min((int)((v.z - bmn) * scale), BINS - 1);
        int b3 = min((int)((v.w - bmn) * scale), BINS - 1);
        atomicAdd(&sh[wid][b0], 1u);
        atomicAdd(&sh[wid][b1], 1u);
        atomicAdd(&sh[wid][b2], 1u);
        atomicAdd(&sh[wid][b3], 1u);
    }
    __syncthreads();

    int c3 = ch % 3, bs = ch / 3;
    for (int bin = tid; bin < BINS; bin += 256) {
        unsigned s = 0;
        #pragma unroll
        for (int w = 0; w < 8; w++) s += sh[w][bin];
        g_hist[bs * 300 + c3 * BINS + bin] = (float)s;
    }
}

// ---------------- kernel 2: big GEMM (xm = x @ base_W^T), split-K partials ----------------
__global__ void __launch_bounds__(256, 2)
gemm_big(const float* __restrict__ x, const float* __restrict__ W) {
    extern __shared__ float smem[];
    float* As = smem;                 // [2][64][36]
    float* Bs = smem + 2 * A_CH;      // [2][256][36]

    int tid  = threadIdx.x;
    int wid  = tid >> 5, lane = tid & 31;
    int wm   = wid >> 2;
    int wn   = wid & 3;
    int g    = lane >> 2, t = lane & 3;

    int nbase = blockIdx.x * NB;
    int kbase = blockIdx.y * KB;

    float acc[2][8][4];
    #pragma unroll
    for (int i = 0; i < 2; i++)
        #pragma unroll
        for (int j = 0; j < 8; j++)
            #pragma unroll
            for (int q = 0; q < 4; q++) acc[i][j][q] = 0.0f;

    auto load_chunk = [&](int buf, int kg) {
        #pragma unroll
        for (int i = 0; i < 2; i++) {
            int f = tid + i * 256;
            int row = f >> 3, seg = f & 7;
            cp16(As + buf * A_CH + row * 36 + seg * 4,
                 x + (size_t)row * K_TOTAL + kg + seg * 4);
        }
        #pragma unroll
        for (int i = 0; i < 8; i++) {
            int f = tid + i * 256;
            int row = f >> 3, seg = f & 7;
            cp16(Bs + buf * B_CH + row * 36 + seg * 4,
                 W + (size_t)(nbase + row) * K_TOTAL + kg + seg * 4);
        }
        cp_commit();
    };

    load_chunk(0, kbase);

    for (int c = 0; c < NCHUNK; c++) {
        int buf = c & 1;
        if (c + 1 < NCHUNK) { load_chunk(buf ^ 1, kbase + (c + 1) * KC); cp_wait1(); }
        else cp_wait0();
        __syncthreads();

        const float* ab = As + buf * A_CH + (wm * 32) * 36;
        const float* bb = Bs + buf * B_CH + (wn * 64) * 36;

        #pragma unroll
        for (int ks = 0; ks < 4; ks++) {
            int kc = ks * 8;
            unsigned a[2][4];
            #pragma unroll
            for (int mf = 0; mf < 2; mf++) {
                const float* ap = ab + (mf * 16 + g) * 36 + kc + t;
                a[mf][0] = __float_as_uint(ap[0]);
                a[mf][1] = __float_as_uint(ap[8 * 36]);
                a[mf][2] = __float_as_uint(ap[4]);
                a[mf][3] = __float_as_uint(ap[8 * 36 + 4]);
            }
            #pragma unroll
            for (int nf = 0; nf < 8; nf++) {
                const float* bp = bb + (nf * 8 + g) * 36 + kc + t;
                unsigned b0 = __float_as_uint(bp[0]);
                unsigned b1 = __float_as_uint(bp[4]);
                mma_tf32(acc[0][nf], a[0], b0, b1);
                mma_tf32(acc[1][nf], a[1], b0, b1);
            }
        }
        __syncthreads();
    }

    size_t ks = blockIdx.y;
    #pragma unroll
    for (int mf = 0; mf < 2; mf++)
        #pragma unroll
        for (int nf = 0; nf < 8; nf++)
            #pragma unroll
            for (int ci = 0; ci < 4; ci++) {
                int b = wm * 32 + mf * 16 + g + ((ci >= 2) ? 8 : 0);
                int n = nbase + wn * 64 + nf * 8 + 2 * t + (ci & 1);
                g_partial[(ks * BATCH + b) * EMB + n] = acc[mf][nf][ci];
            }
}

// ---------------- kernel 3: split-K reduce + assemble hin [64][812] ----------------
__global__ void reduce_kernel(const float* __restrict__ base_b) {
    int tidg = blockIdx.x * 256 + threadIdx.x;
    if (tidg >= BATCH * 812) return;
    int b = tidg / 812, c = tidg - b * 812;
    float v;
    if (c < EMB) {
        float s = base_b[c];
        const float* p = g_partial + (size_t)b * EMB + c;
        #pragma unroll 7
        for (int ks = 0; ks < KSPLIT; ks++) s += p[(size_t)ks * BATCH * EMB];
        v = s;
    } else {
        v = g_hist[b * 300 + (c - EMB)];
    }
    g_hin[tidg] = v;
}

// ---------------- kernel 4: layer1 h = relu(hin @ hW^T + hb), W-tile in smem ----------------
// grid 50 (8 outputs per CTA), 256 threads: thread = (n within 8, b within 32), 2 b per thread
__global__ void layer1_kernel(const float* __restrict__ hW, const float* __restrict__ hb) {
    const int Kq = 203;                       // 812/4, odd -> conflict-free
    __shared__ float4 Ws[8 * 203];
    int n0 = blockIdx.x * 8, tid = threadIdx.x;

    for (int i = tid; i < 8 * Kq; i += 256) {
        int r = i / Kq, q = i - r * Kq;
        Ws[r * Kq + q] = ((const float4*)(hW + (size_t)(n0 + r) * 812))[q];
    }
    __syncthreads();

    int nl = tid & 7, b0 = tid >> 3;          // b0: 0..31
    int n = n0 + nl;
    float bias = hb[n];
    const float4* A0 = (const float4*)(g_hin + (size_t)b0 * 812);
    const float4* A1 = (const float4*)(g_hin + (size_t)(b0 + 32) * 812);
    const float4* Wp = Ws + nl * Kq;

    float acc0 = bias, acc1 = bias;
    #pragma unroll 4
    for (int q = 0; q < Kq; q++) {
        float4 w = Wp[q], a0 = A0[q], a1 = A1[q];
        acc0 += a0.x * w.x + a0.y * w.y + a0.z * w.z + a0.w * w.w;
        acc1 += a1.x * w.x + a1.y * w.y + a1.z * w.z + a1.w * w.w;
    }
    g_h[b0 * 400 + n]        = fmaxf(acc0, 0.0f);
    g_h[(b0 + 32) * 400 + n] = fmaxf(acc1, 0.0f);
}

// ---------------- kernel 5: all head hidden layers as one N=1400 GEMM ----------------
// grid 175 (8 outputs per CTA; 600/1000 boundaries are multiples of 8)
__global__ void heads_hidden_kernel(const float* __restrict__ stW1, const float* __restrict__ stb1,
                                    const float* __restrict__ ageW1, const float* __restrict__ ageb1,
                                    const float* __restrict__ genW1, const float* __restrict__ genb1) {
    const int Kq = 100, SW = 101;             // padded stride -> conflict-free
    __shared__ float4 Ws[8 * 101];
    int n0 = blockIdx.x * 8, tid = threadIdx.x;

    const float *W, *bias;
    int nrel;
    if (n0 < 600)       { W = stW1;  bias = stb1;  nrel = n0; }
    else if (n0 < 1000) { W = ageW1; bias = ageb1; nrel = n0 - 600; }
    else                { W = genW1; bias = genb1; nrel = n0 - 1000; }

    for (int i = tid; i < 8 * Kq; i += 256) {
        int r = i / Kq, q = i - r * Kq;
        Ws[r * SW + q] = ((const float4*)(W + (size_t)(nrel + r) * 400))[q];
    }
    __syncthreads();

    int nl = tid & 7, b0 = tid >> 3;
    float bs = bias[nrel + nl];
    const float4* A0 = (const float4*)(g_h + (size_t)b0 * 400);
    const float4* A1 = (const float4*)(g_h + (size_t)(b0 + 32) * 400);
    const float4* Wp = Ws + nl * SW;

    float acc0 = bs, acc1 = bs;
    #pragma unroll 4
    for (int q = 0; q < Kq; q++) {
        float4 w = Wp[q], a0 = A0[q], a1 = A1[q];
        acc0 += a0.x * w.x + a0.y * w.y + a0.z * w.z + a0.w * w.w;
        acc1 += a1.x * w.x + a1.y * w.y + a1.z * w.z + a1.w * w.w;
    }
    int n = n0 + nl;
    g_hid[b0 * 1400 + n]        = fmaxf(acc0, 0.0f);
    g_hid[(b0 + 32) * 1400 + n] = fmaxf(acc1, 0.0f);
}

// ---------------- kernel 6: logits + softmax, all heads ----------------
// grid 64 (one CTA per sample), 256 threads: warp per logit (16 logits total)
__global__ void logits_kernel(const float* __restrict__ stW2, const float* __restrict__ stb2,
                              const float* __restrict__ ageW2, const float* __restrict__ ageb2,
                              const float* __restrict__ genW2, const float* __restrict__ genb2,
                              float* __restrict__ out) {
    int b = blockIdx.x, tid = threadIdx.x;
    int wid = tid >> 5, lane = tid & 31;
    __shared__ float lg[16];
    const float* hid = g_hid + (size_t)b * 1400;

    for (int idx = wid; idx < 16; idx += 8) {
        const float *w, *hp;
        int K; float bias;
        if (idx < 10)      { w = stW2  + idx * 600;        hp = hid;        K = 600; bias = stb2[idx]; }
        else if (idx < 14) { w = ageW2 + (idx - 10) * 400; hp = hid + 600;  K = 400; bias = ageb2[idx - 10]; }
        else               { w = genW2 + (idx - 14) * 400; hp = hid + 1000; K = 400; bias = genb2[idx - 14]; }
        float p = 0.0f;
        for (int k = lane; k < K; k += 32) p += hp[k] * w[k];
        #pragma unroll
        for (int o = 16; o; o >>= 1) p += __shfl_xor_sync(0xFFFFFFFFu, p, o);
        if (lane == 0) lg[idx] = fmaxf(p + bias, 0.0f);
    }
    __syncthreads();

    if (tid < 3) {
        int off = (tid == 0) ? 0 : (tid == 1) ? 10 : 14;
        int NL  = (tid == 0) ? 10 : (tid == 1) ? 4 : 2;
        float* outp = (tid == 0) ? out + b * 10
                    : (tid == 1) ? out + 640 + b * 4
                                 : out + 896 + b * 2;
        float m = lg[off];
        for (int n = 1; n < NL; n++) m = fmaxf(m, lg[off + n]);
        float e[10], s = 0.0f;
        for (int n = 0; n < NL; n++) { e[n] = __expf(lg[off + n] - m); s += e[n]; }
        float inv = 1.0f / s;
        for (int n = 0; n < NL; n++) outp[n] = e[n] * inv;
    }
}

// ---------------- launch ----------------
extern "C" void kernel_launch(void* const* d_in, const int* in_sizes, int n_in,
                              void* d_out, int out_size) {
    const float* x      = (const float*)d_in[0];
    const float* base_W = (const float*)d_in[1];
    const float* base_b = (const float*)d_in[2];
    const float* hW     = (const float*)d_in[3];
    const float* hb     = (const float*)d_in[4];
    const float* stW1   = (const float*)d_in[5];
    const float* stb1   = (const float*)d_in[6];
    const float* stW2   = (const float*)d_in[7];
    const float* stb2   = (const float*)d_in[8];
    const float* ageW1  = (const float*)d_in[9];
    const float* ageb1  = (const float*)d_in[10];
    const float* ageW2  = (const float*)d_in[11];
    const float* ageb2  = (const float*)d_in[12];
    const float* genW1  = (const float*)d_in[13];
    const float* genb1  = (const float*)d_in[14];
    const float* genW2  = (const float*)d_in[15];
    const float* genb2  = (const float*)d_in[16];
    float* out = (float*)d_out;

    cudaFuncSetAttribute(gemm_big, cudaFuncAttributeMaxDynamicSharedMemorySize, SMEM_BYTES);

    hist_fused_kernel<<<NCHAN, 256>>>(x);
    gemm_big<<<dim3(2, KSPLIT), 256, SMEM_BYTES>>>(x, base_W);
    reduce_kernel<<<(BATCH * 812 + 255) / 256, 256>>>(base_b);
    layer1_kernel<<<50, 256>>>(hW, hb);
    heads_hidden_kernel<<<175, 256>>>(stW1, stb1, ageW1, ageb1, genW1, genb1);
    logits_kernel<<<BATCH, 256>>>(stW2, stb2, ageW2, ageb2, genW2, genb2, out);
}

// round 12
// speedup vs baseline: 2.7219x; 1.1765x over previous
#include <cuda_runtime.h>
#include <cuda_bf16.h>
#include <cstdint>
#include <math.h>

// ---------------- problem constants ----------------
#define K_TOTAL 150528      // 3*224*224
#define BATCH   64
#define EMB     512
#define NCHAN   192         // 64*3
#define NPIX    50176       // 224*224
#define BINS    100

// big GEMM tiling
#define KSPLIT  147
#define KB      1024        // K per CTA (147*1024 = 150528)
#define KC      32          // K per smem chunk
#define NCHUNK  (KB/KC)     // 32
#define NB      256         // N per CTA (2 CTAs cover 512)
#define A_CH    (64*36)     // floats per A chunk buffer (padded)
#define B_CH    (256*36)    // floats per B chunk buffer (padded)
#define SMEM_BYTES ((2*A_CH + 2*B_CH)*4)   // 92160

// layer1 tile
#define L1_NT   16          // outputs per warp
#define L1_KQ   203         // 812/4 float4 per row
#define L1_SMEM (L1_NT * 812 * 4)   // 51968 B dynamic

// ---------------- static device scratch (no runtime alloc) ----------------
__device__ float g_partial[(size_t)KSPLIT * BATCH * EMB];   // [ks][b][n] 19.3MB
__device__ float g_hist[BATCH * 300];                       // [64][300]
__device__ float g_hin[BATCH * 812];                        // [64][812]
__device__ float g_h[BATCH * 400];                          // [64][400]
__device__ float g_hid[BATCH * 1400];                       // [64][st600|age400|gen400]

// ---------------- helpers ----------------
__device__ __forceinline__ void cp16(void* dst, const void* src) {
    unsigned d = (unsigned)__cvta_generic_to_shared(dst);
    asm volatile("cp.async.cg.shared.global [%0], [%1], 16;\n" :: "r"(d), "l"(src));
}
__device__ __forceinline__ void cp_commit() { asm volatile("cp.async.commit_group;\n"); }
__device__ __forceinline__ void cp_wait1()  { asm volatile("cp.async.wait_group 1;\n"); }
__device__ __forceinline__ void cp_wait0()  { asm volatile("cp.async.wait_group 0;\n"); }

__device__ __forceinline__ void mma_tf32(float* c, const unsigned* a, unsigned b0, unsigned b1) {
    asm volatile(
        "mma.sync.aligned.m16n8k8.row.col.f32.tf32.tf32.f32 "
        "{%0,%1,%2,%3}, {%4,%5,%6,%7}, {%8,%9}, {%0,%1,%2,%3};\n"
        : "+f"(c[0]), "+f"(c[1]), "+f"(c[2]), "+f"(c[3])
        : "r"(a[0]), "r"(a[1]), "r"(a[2]), "r"(a[3]), "r"(b0), "r"(b1));
}

__device__ __forceinline__ float warp_sum(float v) {
    #pragma unroll
    for (int o = 16; o; o >>= 1) v += __shfl_xor_sync(0xFFFFFFFFu, v, o);
    return v;
}

// ---------------- kernel 1: fused per-channel min/max + 100-bin histogram ----------------
__global__ void hist_fused_kernel(const float* __restrict__ x) {
    int ch = blockIdx.x;
    int tid = threadIdx.x, wid = tid >> 5;
    const float4* p = (const float4*)(x + (size_t)ch * NPIX);

    __shared__ unsigned sh[8][BINS];
    __shared__ float smn[8], smx[8];
    __shared__ float s_mn, s_scale;

    for (int i = tid; i < 8 * BINS; i += 256) ((unsigned*)sh)[i] = 0u;

    float mn = 3.4e38f, mx = -3.4e38f;
    for (int i = tid; i < NPIX / 4; i += 256) {
        float4 v = p[i];
        mn = fminf(mn, fminf(fminf(v.x, v.y), fminf(v.z, v.w)));
        mx = fmaxf(mx, fmaxf(fmaxf(v.x, v.y), fmaxf(v.z, v.w)));
    }
    #pragma unroll
    for (int o = 16; o; o >>= 1) {
        mn = fminf(mn, __shfl_xor_sync(0xFFFFFFFFu, mn, o));
        mx = fmaxf(mx, __shfl_xor_sync(0xFFFFFFFFu, mx, o));
    }
    if ((tid & 31) == 0) { smn[wid] = mn; smx[wid] = mx; }
    __syncthreads();
    if (tid == 0) {
        #pragma unroll
        for (int r = 1; r < 8; r++) { mn = fminf(mn, smn[r]); mx = fmaxf(mx, smx[r]); }
        float width = (mx > mn) ? (mx - mn) : 1.0f;
        s_mn = mn;
        s_scale = (float)BINS / width;
    }
    __syncthreads();

    float bmn = s_mn, scale = s_scale;
    for (int i = tid; i < NPIX / 4; i += 256) {
        float4 v = p[i];
        int b0 = min((int)((v.x - bmn) * scale), BINS - 1);
        int b1 = min((int)((v.y - bmn) * scale), BINS - 1);
        int b2 = min((int)((v.z - bmn) * scale), BINS - 1);
        int b3 = min((int)((v.w - bmn) * scale), BINS - 1);
        atomicAdd(&sh[wid][b0], 1u);
        atomicAdd(&sh[wid][b1], 1u);
        atomicAdd(&sh[wid][b2], 1u);
        atomicAdd(&sh[wid][b3], 1u);
    }
    __syncthreads();

    int c3 = ch % 3, bs = ch / 3;
    for (int bin = tid; bin < BINS; bin += 256) {
        unsigned s = 0;
        #pragma unroll
        for (int w = 0; w < 8; w++) s += sh[w][bin];
        g_hist[bs * 300 + c3 * BINS + bin] = (float)s;
    }
}

// ---------------- kernel 2: big GEMM (xm = x @ base_W^T), split-K partials ----------------
__global__ void __launch_bounds__(256, 2)
gemm_big(const float* __restrict__ x, const float* __restrict__ W) {
    extern __shared__ float smem[];
    float* As = smem;                 // [2][64][36]
    float* Bs = smem + 2 * A_CH;      // [2][256][36]

    int tid  = threadIdx.x;
    int wid  = tid >> 5, lane = tid & 31;
    int wm   = wid >> 2;
    int wn   = wid & 3;
    int g    = lane >> 2, t = lane & 3;

    int nbase = blockIdx.x * NB;
    int kbase = blockIdx.y * KB;

    float acc[2][8][4];
    #pragma unroll
    for (int i = 0; i < 2; i++)
        #pragma unroll
        for (int j = 0; j < 8; j++)
            #pragma unroll
            for (int q = 0; q < 4; q++) acc[i][j][q] = 0.0f;

    auto load_chunk = [&](int buf, int kg) {
        #pragma unroll
        for (int i = 0; i < 2; i++) {
            int f = tid + i * 256;
            int row = f >> 3, seg = f & 7;
            cp16(As + buf * A_CH + row * 36 + seg * 4,
                 x + (size_t)row * K_TOTAL + kg + seg * 4);
        }
        #pragma unroll
        for (int i = 0; i < 8; i++) {
            int f = tid + i * 256;
            int row = f >> 3, seg = f & 7;
            cp16(Bs + buf * B_CH + row * 36 + seg * 4,
                 W + (size_t)(nbase + row) * K_TOTAL + kg + seg * 4);
        }
        cp_commit();
    };

    load_chunk(0, kbase);

    for (int c = 0; c < NCHUNK; c++) {
        int buf = c & 1;
        if (c + 1 < NCHUNK) { load_chunk(buf ^ 1, kbase + (c + 1) * KC); cp_wait1(); }
        else cp_wait0();
        __syncthreads();

        const float* ab = As + buf * A_CH + (wm * 32) * 36;
        const float* bb = Bs + buf * B_CH + (wn * 64) * 36;

        #pragma unroll
        for (int ks = 0; ks < 4; ks++) {
            int kc = ks * 8;
            unsigned a[2][4];
            #pragma unroll
            for (int mf = 0; mf < 2; mf++) {
                const float* ap = ab + (mf * 16 + g) * 36 + kc + t;
                a[mf][0] = __float_as_uint(ap[0]);
                a[mf][1] = __float_as_uint(ap[8 * 36]);
                a[mf][2] = __float_as_uint(ap[4]);
                a[mf][3] = __float_as_uint(ap[8 * 36 + 4]);
            }
            #pragma unroll
            for (int nf = 0; nf < 8; nf++) {
                const float* bp = bb + (nf * 8 + g) * 36 + kc + t;
                unsigned b0 = __float_as_uint(bp[0]);
                unsigned b1 = __float_as_uint(bp[4]);
                mma_tf32(acc[0][nf], a[0], b0, b1);
                mma_tf32(acc[1][nf], a[1], b0, b1);
            }
        }
        __syncthreads();
    }

    size_t ks = blockIdx.y;
    #pragma unroll
    for (int mf = 0; mf < 2; mf++)
        #pragma unroll
        for (int nf = 0; nf < 8; nf++)
            #pragma unroll
            for (int ci = 0; ci < 4; ci++) {
                int b = wm * 32 + mf * 16 + g + ((ci >= 2) ? 8 : 0);
                int n = nbase + wn * 64 + nf * 8 + 2 * t + (ci & 1);
                g_partial[(ks * BATCH + b) * EMB + n] = acc[mf][nf][ci];
            }
}

// ---------------- kernel 3: split-K reduce + assemble hin [64][812] ----------------
__global__ void reduce_kernel(const float* __restrict__ base_b) {
    int tidg = blockIdx.x * 256 + threadIdx.x;
    if (tidg >= BATCH * 812) return;
    int b = tidg / 812, c = tidg - b * 812;
    float v;
    if (c < EMB) {
        float s = base_b[c];
        const float* p = g_partial + (size_t)b * EMB + c;
        #pragma unroll 7
        for (int ks = 0; ks < KSPLIT; ks++) s += p[(size_t)ks * BATCH * EMB];
        v = s;
    } else {
        v = g_hist[b * 300 + (c - EMB)];
    }
    g_hin[tidg] = v;
}

// ---------------- kernel 4: layer1 (warp = 1 batch row x 16 outputs, lanes split K) ----------------
// grid (25 n-tiles, 8 b-tiles), 256 threads (8 warps), dynamic smem L1_SMEM
__global__ void layer1_kernel(const float* __restrict__ hW, const float* __restrict__ hb) {
    extern __shared__ float4 Ws4[];          // [16][203] float4
    int tid = threadIdx.x, lane = tid & 31, w = tid >> 5;
    int n0 = blockIdx.x * L1_NT;
    int b  = blockIdx.y * 8 + w;

    // load W tile [16][812]
    for (int i = tid; i < L1_NT * L1_KQ; i += 256) {
        int r = i / L1_KQ, q = i - r * L1_KQ;
        Ws4[r * L1_KQ + q] = ((const float4*)(hW + (size_t)(n0 + r) * 812))[q];
    }
    __syncthreads();

    const float4* Arow = (const float4*)(g_hin + (size_t)b * 812);

    float acc[L1_NT];
    #pragma unroll
    for (int n = 0; n < L1_NT; n++) acc[n] = 0.0f;

    #pragma unroll
    for (int iter = 0; iter < 7; iter++) {
        int idx = iter * 32 + lane;
        if (idx < L1_KQ) {
            float4 a = Arow[idx];
            #pragma unroll
            for (int n = 0; n < L1_NT; n++) {
                float4 wv = Ws4[n * L1_KQ + idx];
                acc[n] += a.x * wv.x + a.y * wv.y + a.z * wv.z + a.w * wv.w;
            }
        }
    }

    #pragma unroll
    for (int n = 0; n < L1_NT; n++) {
        float s = warp_sum(acc[n]);
        if (lane == n) g_h[(size_t)b * 400 + n0 + n] = fmaxf(s + hb[n0 + n], 0.0f);
    }
}

// ---------------- kernel 5: head hidden layers (warp = 1 b x 8 outputs, lanes split K=400) ----------------
// grid (175 n-tiles, 8 b-tiles), 256 threads
__global__ void heads_hidden_kernel(const float* __restrict__ stW1, const float* __restrict__ stb1,
                                    const float* __restrict__ ageW1, const float* __restrict__ ageb1,
                                    const float* __restrict__ genW1, const float* __restrict__ genb1) {
    __shared__ float4 Ws4[8 * 100];          // [8][100] float4 = 12.8KB
    int tid = threadIdx.x, lane = tid & 31, w = tid >> 5;
    int n0 = blockIdx.x * 8;                 // global n in [0,1400), 8-aligned
    int b  = blockIdx.y * 8 + w;

    const float *W, *bias;
    int nrel;
    if (n0 < 600)       { W = stW1;  bias = stb1;  nrel = n0; }
    else if (n0 < 1000) { W = ageW1; bias = ageb1; nrel = n0 - 600; }
    else                { W = genW1; bias = genb1; nrel = n0 - 1000; }

    for (int i = tid; i < 8 * 100; i += 256) {
        int r = i / 100, q = i - r * 100;
        Ws4[r * 100 + q] = ((const float4*)(W + (size_t)(nrel + r) * 400))[q];
    }
    __syncthreads();

    const float4* Arow = (const float4*)(g_h + (size_t)b * 400);

    float acc[8];
    #pragma unroll
    for (int n = 0; n < 8; n++) acc[n] = 0.0f;

    #pragma unroll
    for (int iter = 0; iter < 4; iter++) {
        int idx = iter * 32 + lane;
        if (idx < 100) {
            float4 a = Arow[idx];
            #pragma unroll
            for (int n = 0; n < 8; n++) {
                float4 wv = Ws4[n * 100 + idx];
                acc[n] += a.x * wv.x + a.y * wv.y + a.z * wv.z + a.w * wv.w;
            }
        }
    }

    #pragma unroll
    for (int n = 0; n < 8; n++) {
        float s = warp_sum(acc[n]);
        if (lane == n) g_hid[(size_t)b * 1400 + n0 + n] = fmaxf(s + bias[nrel + n], 0.0f);
    }
}

// ---------------- kernel 6: logits + softmax, all heads ----------------
__global__ void logits_kernel(const float* __restrict__ stW2, const float* __restrict__ stb2,
                              const float* __restrict__ ageW2, const float* __restrict__ ageb2,
                              const float* __restrict__ genW2, const float* __restrict__ genb2,
                              float* __restrict__ out) {
    int b = blockIdx.x, tid = threadIdx.x;
    int wid = tid >> 5, lane = tid & 31;
    __shared__ float lg[16];
    const float* hid = g_hid + (size_t)b * 1400;

    for (int idx = wid; idx < 16; idx += 8) {
        const float *w, *hp;
        int K; float bias;
        if (idx < 10)      { w = stW2  + idx * 600;        hp = hid;        K = 600; bias = stb2[idx]; }
        else if (idx < 14) { w = ageW2 + (idx - 10) * 400; hp = hid + 600;  K = 400; bias = ageb2[idx - 10]; }
        else               { w = genW2 + (idx - 14) * 400; hp = hid + 1000; K = 400; bias = genb2[idx - 14]; }
        float p = 0.0f;
        for (int k = lane; k < K; k += 32) p += hp[k] * w[k];
        #pragma unroll
        for (int o = 16; o; o >>= 1) p += __shfl_xor_sync(0xFFFFFFFFu, p, o);
        if (lane == 0) lg[idx] = fmaxf(p + bias, 0.0f);
    }
    __syncthreads();

    if (tid < 3) {
        int off = (tid == 0) ? 0 : (tid == 1) ? 10 : 14;
        int NL  = (tid == 0) ? 10 : (tid == 1) ? 4 : 2;
        float* outp = (tid == 0) ? out + b * 10
                    : (tid == 1) ? out + 640 + b * 4
                                 : out + 896 + b * 2;
        float m = lg[off];
        for (int n = 1; n < NL; n++) m = fmaxf(m, lg[off + n]);
        float e[10], s = 0.0f;
        for (int n = 0; n < NL; n++) { e[n] = __expf(lg[off + n] - m); s += e[n]; }
        float inv = 1.0f / s;
        for (int n = 0; n < NL; n++) outp[n] = e[n] * inv;
    }
}

// ---------------- launch ----------------
extern "C" void kernel_launch(void* const* d_in, const int* in_sizes, int n_in,
                              void* d_out, int out_size) {
    const float* x      = (const float*)d_in[0];
    const float* base_W = (const float*)d_in[1];
    const float* base_b = (const float*)d_in[2];
    const float* hW     = (const float*)d_in[3];
    const float* hb     = (const float*)d_in[4];
    const float* stW1   = (const float*)d_in[5];
    const float* stb1   = (const float*)d_in[6];
    const float* stW2   = (const float*)d_in[7];
    const float* stb2   = (const float*)d_in[8];
    const float* ageW1  = (const float*)d_in[9];
    const float* ageb1  = (const float*)d_in[10];
    const float* ageW2  = (const float*)d_in[11];
    const float* ageb2  = (const float*)d_in[12];
    const float* genW1  = (const float*)d_in[13];
    const float* genb1  = (const float*)d_in[14];
    const float* genW2  = (const float*)d_in[15];
    const float* genb2  = (const float*)d_in[16];
    float* out = (float*)d_out;

    cudaFuncSetAttribute(gemm_big, cudaFuncAttributeMaxDynamicSharedMemorySize, SMEM_BYTES);
    cudaFuncSetAttribute(layer1_kernel, cudaFuncAttributeMaxDynamicSharedMemorySize, L1_SMEM);

    hist_fused_kernel<<<NCHAN, 256>>>(x);
    gemm_big<<<dim3(2, KSPLIT), 256, SMEM_BYTES>>>(x, base_W);
    reduce_kernel<<<(BATCH * 812 + 255) / 256, 256>>>(base_b);
    layer1_kernel<<<dim3(25, 8), 256, L1_SMEM>>>(hW, hb);
    heads_hidden_kernel<<<dim3(175, 8), 256>>>(stW1, stb1, ageW1, ageb1, genW1, genb1);
    logits_kernel<<<BATCH, 256>>>(stW2, stb2, ageW2, ageb2, genW2, genb2, out);
}